// round 13
// baseline (speedup 1.0000x reference)
#include <cuda_runtime.h>
#include <cuda_fp16.h>
#include <cstdint>

typedef unsigned int u32;
typedef unsigned long long u64;

#define F       128
#define NI      31
#define NL      32
#define TMAX    20
#define NGROUP  5            // 5 groups x 4 trees (128 node-cols per group)
#define TILE_M  128
#define NTHREADS 256

// ---- SMEM layout (bytes) ----
// X: 64 pair-regions (8 mtblocks x 8 pairs) x 512B. Quad (16B) = full A fragment:
//    [row p: w0,w1 | row p+8: w0,w1] for one kb. Physical quad = (kb*4+t4) ^ (parity*4).
// W: 128 rows x 256B. Quad = B fragments of kb-pair j: [kb2j: w0,w1 | kb2j+1: w0,w1].
//    Physical quad = (j*4+t4) ^ (parity*4). parity = row/pair low bit (== gid&1 for readers).
#define X_OFF  0             // 32768
#define W_OFF  32768         // 32768
#define L_OFF  65536         // 128 rows * 20 quads * 16B = 40960 (fp16 half-logits, quad-swizzled)
#define SMEM_BYTES 106496
// L quad layout: quad = row*20 + tree*4 + (t4 ^ ((row>>1)&3)); quad holds 4 h2 (nt=0..3)

// __device__ scratch (allocation-free)
__device__ __half g_Wh[NGROUP * 128 * F];  // fp16 HALVED masked weights, fragment-packed rows (256B)
__device__ float  g_bs[TMAX * 32];         // 0.5*bias, padded to 32 nodes
__device__ float  g_lc[TMAX * 32];         // leaf pairs: {base_l, delta_l} for class 0
__device__ float  g_wt[TMAX];              // softmax tree weight

__constant__ float c_bs05[TMAX * 32];
__constant__ float c_lc[TMAX * 32];
__constant__ float c_wt[TMAX];

// ---------------- helpers ----------------
__device__ __forceinline__ u32 smem_u32(const void* p) {
    u32 a;
    asm("{ .reg .u64 t; cvta.to.shared.u64 t, %1; cvt.u32.u64 %0, t; }" : "=r"(a) : "l"(p));
    return a;
}
__device__ __forceinline__ u32 pack_h2(float lo, float hi) {
    u32 r;
    asm("cvt.rn.f16x2.f32 %0, %1, %2;" : "=r"(r) : "f"(hi), "f"(lo));
    return r;
}
__device__ __forceinline__ void cpa16(u32 dst, const void* src) {
    asm volatile("cp.async.cg.shared.global [%0], [%1], 16;" :: "r"(dst), "l"(src) : "memory");
}
#define CP_COMMIT() asm volatile("cp.async.commit_group;" ::: "memory")
template<int N> __device__ __forceinline__ void cp_wait() {
    asm volatile("cp.async.wait_group %0;" :: "n"(N) : "memory");
}
__device__ __forceinline__ void lds_v4(u32& a, u32& b, u32& c, u32& d, u32 addr) {
    asm volatile("ld.shared.v4.u32 {%0,%1,%2,%3}, [%4];"
                 : "=r"(a), "=r"(b), "=r"(c), "=r"(d) : "r"(addr));
}
__device__ __forceinline__ void sts_v4(u32 addr, u32 a, u32 b, u32 c, u32 d) {
    asm volatile("st.shared.v4.u32 [%0], {%1,%2,%3,%4};"
                 :: "r"(addr), "r"(a), "r"(b), "r"(c), "r"(d) : "memory");
}

// m16n8k16 f16 MMA, fp32 accum.
#define MMA_F16(c, a0, a1, a2, a3, b0, b1) \
    asm volatile("mma.sync.aligned.m16n8k16.row.col.f32.f16.f16.f32 " \
        "{%0,%1,%2,%3}, {%4,%5,%6,%7}, {%8,%9}, {%0,%1,%2,%3};" \
        : "+f"((c)[0]), "+f"((c)[1]), "+f"((c)[2]), "+f"((c)[3]) \
        : "r"(a0), "r"(a1), "r"(a2), "r"(a3), "r"(b0), "r"(b1))

// ---------------- prologue ----------------
// W row layout (128 fp16): quad (j,t4) at fp16 [ (j*4+t4)*8 .. +8 ):
//   [kb=2j word0(2), word1(2), kb=2j+1 word0(2), word1(2)]
// where word0 of kb = k{2t4,2t4+1}, word1 = k{2t4+8,2t4+9}.
__global__ void prep(const float* __restrict__ sw, const float* __restrict__ fm,
                     const float* __restrict__ sb,
                     const float* __restrict__ ll, const float* __restrict__ tw, int T) {
    int idx = blockIdx.x * 256 + threadIdx.x;
    const int total = NGROUP * 128 * F;   // 81920
    if (idx < total) {
        int k    = idx & 127;
        int nrow = (idx >> 7) & 127;
        int g    = idx >> 14;
        int t    = g * 4 + (nrow >> 5);
        int n    = nrow & 31;
        float v = 0.f;
        if (t < T && n < NI) v = 0.5f * sw[(t * NI + n) * F + k] * fm[t * F + k];
        int k16 = k & 15;
        int j    = k >> 5;
        int kbh  = (k >> 4) & 1;
        int t4   = (k16 & 7) >> 1;
        int wslot = (k16 >> 3) & 1;
        int lo   = k16 & 1;
        int slot = (j * 4 + t4) * 8 + kbh * 4 + wslot * 2 + lo;
        g_Wh[(idx & ~127) + slot] = __float2half_rn(v);
    }
    if (idx < TMAX * 32) {   // halved bias, node 31 padded to 0
        int t = idx >> 5, n = idx & 31;
        g_bs[idx] = (t < T && n < NI) ? 0.5f * sb[t * NI + n] : 0.f;
    }
    if (idx < TMAX * 16) {   // leaf lerp constants (class 0)
        int t = idx >> 4, l = idx & 15;
        float base = 0.f, delta = 0.f;
        if (t < T) {
            float m = -1e30f;
            for (int k = 0; k < T; k++) m = fmaxf(m, tw[k]);
            float den = 0.f;
            for (int k = 0; k < T; k++) den += expf(tw[k] - m);
            float w = expf(tw[t] - m) / den;
            float a0 = ll[(t * NL + 2 * l) * 2 + 0], b0 = ll[(t * NL + 2 * l) * 2 + 1];
            float a1 = ll[(t * NL + 2 * l + 1) * 2 + 0], b1 = ll[(t * NL + 2 * l + 1) * 2 + 1];
            float m0 = fmaxf(a0, b0), m1 = fmaxf(a1, b1);
            float e0 = expf(a0 - m0), f0 = expf(b0 - m0);
            float e1 = expf(a1 - m1), f1 = expf(b1 - m1);
            float p0 = w * e0 / (e0 + f0);
            float p1 = w * e1 / (e1 + f1);
            base = p0; delta = p1 - p0;
        }
        g_lc[t * 32 + 2 * l + 0] = base;
        g_lc[t * 32 + 2 * l + 1] = delta;
    }
    if (idx < TMAX) {        // tree weights
        float w = 0.f;
        if (idx < T) {
            float m = -1e30f;
            for (int k = 0; k < T; k++) m = fmaxf(m, tw[k]);
            float den = 0.f;
            for (int k = 0; k < T; k++) den += expf(tw[k] - m);
            w = expf(tw[idx] - m) / den;
        }
        g_wt[idx] = w;
    }
}

// ---------------- main fused kernel ----------------
__global__ void __launch_bounds__(NTHREADS, 2) forest_mma(
    const float* __restrict__ x, float* __restrict__ out, int B)
{
    extern __shared__ char smem[];
    float* smf = (float*)smem;
    const u32 sbase = smem_u32(smem);
    const int tid  = threadIdx.x;
    const int lane = tid & 31;
    const int wid  = tid >> 5;
    const int gid  = lane >> 2;
    const int tid4 = lane & 3;
    const int warp_m = wid & 1;      // 2 M-groups of 64 rows
    const int warp_n = wid >> 1;     // 4 N-groups of 32 cols (= tree-in-group)
    const int m0 = blockIdx.x * TILE_M;

    // ---- cp.async W group 0 (physical-quad swizzled dst) ----
    {
        const __half* src = g_Wh;
        #pragma unroll
        for (int j = 0; j < 8; j++) {
            int i = tid + j * NTHREADS;           // 2048 chunks: row = i>>4, quad c = i&15
            int row = i >> 4, c = i & 15;
            u32 dst = sbase + W_OFF + (u32)(row * 256) + (u32)((c ^ ((row & 1) * 4)) * 16);
            cpa16(dst, src + row * F + c * 8);
        }
        CP_COMMIT();
    }

    // ---- stage X: LDG float4 -> fp16 pairs into fragment-packed quads ----
    {
        #pragma unroll
        for (int j = 0; j < 16; j++) {
            int i = tid + j * NTHREADS;           // 4096 float4: row = i>>5, c = i&31
            int row = i >> 5, c = i & 31;
            int srow = m0 + row; if (srow >= B) srow = B - 1;
            float4 v = ((const float4*)(x + (size_t)srow * F))[c];
            u32 h01 = pack_h2(v.x, v.y);
            u32 h23 = pack_h2(v.z, v.w);
            int kb = c >> 2, jj = c & 3;
            int t4a   = (jj & 1) * 2;             // h01 owner t4; h23 owner = t4a+1
            int wslot = jj >> 1;
            int pr    = (row >> 4) * 8 + (row & 7);   // pair-region
            int half  = (row >> 3) & 1;
            int qp    = (kb * 4 + t4a) ^ ((row & 1) * 4);
            u32 addr = sbase + X_OFF + (u32)(pr * 512 + qp * 16 + half * 8 + wslot * 4);
            asm volatile("st.shared.u32 [%0], %1;" :: "r"(addr), "r"(h01));
            asm volatile("st.shared.u32 [%0], %1;" :: "r"(addr + 16), "r"(h23));
        }
    }

    // fragment bases
    const u32 g64   = (u32)((gid & 1) << 6);
    const u32 Abase = sbase + X_OFF + (u32)(warp_m * 16384 + gid * 512 + tid4 * 16);
    const u32 Bbase = sbase + W_OFF + (u32)((warp_n * 32 + gid) * 256 + tid4 * 16);

    // reader identity: row r, tree pair
    const int r    = tid & 127;
    const int jhi  = tid >> 7;             // 0/1 -> trees {0,1} or {2,3} of group
    const int sr   = (r >> 1) & 3;         // quad swizzle key for this row (L buffer)
    const u32 Rrow = sbase + L_OFF + (u32)(r * 20 * 16);

    float oc0 = 0.f, oc1 = 0.f;

    #pragma unroll 1
    for (int g = 0; g < NGROUP; g++) {
        cp_wait<0>();
        __syncthreads();             // W(g) (+X on g=0) visible; L(g-1) reads done

        // ================= GEMM(g): acc starts at 0.5*bias =================
        float acc[4][4][4];
        {
            const float* bsp = c_bs05 + ((g * 4 + warp_n) * 32 + tid4 * 2);
            #pragma unroll
            for (int nt = 0; nt < 4; nt++) {
                float b0 = bsp[nt * 8], b1 = bsp[nt * 8 + 1];
                #pragma unroll
                for (int mt = 0; mt < 4; mt++) {
                    acc[mt][nt][0] = b0; acc[mt][nt][1] = b1;
                    acc[mt][nt][2] = b0; acc[mt][nt][3] = b1;
                }
            }
        }

        #pragma unroll
        for (int j = 0; j < 4; j++) {         // logical kb-pair
            const u32 boff = ((u32)(j << 6)) ^ g64;
            u32 b[4][4];
            #pragma unroll
            for (int nt = 0; nt < 4; nt++)
                lds_v4(b[nt][0], b[nt][1], b[nt][2], b[nt][3],
                       Bbase + (u32)(nt * 2048) + boff);
            #pragma unroll
            for (int e = 0; e < 2; e++) {     // logical kb = 2j+e
                const u32 aoff = (u32)(j * 128) + (((u32)(e << 6)) ^ g64);
                #pragma unroll
                for (int mt = 0; mt < 4; mt++) {
                    u32 u0, u1, u2, u3;
                    lds_v4(u0, u1, u2, u3, Abase + (u32)(mt * 4096) + aoff);
                    #pragma unroll
                    for (int nt = 0; nt < 4; nt++)
                        MMA_F16(acc[mt][nt], u0, u2, u1, u3, b[nt][2 * e], b[nt][2 * e + 1]);
                }
            }
        }

        __syncthreads();             // W(g) reads complete -> buffer free

        // prefetch W(g+1) (overlaps logits store + epilogue)
        if (g < NGROUP - 1) {
            const __half* src = g_Wh + (size_t)(g + 1) * 128 * F;
            #pragma unroll
            for (int j = 0; j < 8; j++) {
                int i = tid + j * NTHREADS;
                int row = i >> 4, c = i & 15;
                u32 dst = sbase + W_OFF + (u32)(row * 256) + (u32)((c ^ ((row & 1) * 4)) * 16);
                cpa16(dst, src + row * F + c * 8);
            }
            CP_COMMIT();
        }

        // ---- pack fp16 half-logits, STS.128 (8 per thread, conflict-free) ----
        #pragma unroll
        for (int mt = 0; mt < 4; mt++) {
            #pragma unroll
            for (int half = 0; half < 2; half++) {
                const int row = warp_m * 64 + mt * 16 + half * 8 + gid;
                u32 h0 = pack_h2(acc[mt][0][2 * half], acc[mt][0][2 * half + 1]);
                u32 h1 = pack_h2(acc[mt][1][2 * half], acc[mt][1][2 * half + 1]);
                u32 h2 = pack_h2(acc[mt][2][2 * half], acc[mt][2][2 * half + 1]);
                u32 h3 = pack_h2(acc[mt][3][2 * half], acc[mt][3][2 * half + 1]);
                u32 quad = (u32)(row * 20 + warp_n * 4 + (tid4 ^ ((row >> 1) & 3)));
                sts_v4(sbase + L_OFF + quad * 16, h0, h1, h2, h3);
            }
        }
        __syncthreads();             // logits(g) visible

        // ---- epilogue: 2 (row, tree) tasks per thread ----
        #pragma unroll
        for (int j2 = 0; j2 < 2; j2++) {
            const int tp = jhi * 2 + j2;        // tree-in-group 0..3
            const int t  = g * 4 + tp;
            const float* lc = c_lc + t * 32;
            float s[32];
            #pragma unroll
            for (int q = 0; q < 4; q++) {       // logical quad = writer's tid4
                u32 w0, w1, w2, w3;
                lds_v4(w0, w1, w2, w3, Rrow + (u32)(tp * 4 + (q ^ sr)) * 16);
                const u32 ws[4] = {w0, w1, w2, w3};
                #pragma unroll
                for (int nt = 0; nt < 4; nt++) {
                    __half2 hv = *(__half2*)&ws[nt];
                    const int n = nt * 8 + 2 * q;
                    s[n]     = __low2float(hv);
                    s[n + 1] = __high2float(hv);
                }
            }
            // values are l/2 -> sigmoid = 0.5*tanh + 0.5
            #pragma unroll
            for (int n = 0; n < NI; n++) {
                float th;
                asm("tanh.approx.f32 %0, %1;" : "=f"(th) : "f"(s[n]));
                s[n] = fmaf(0.5f, th, 0.5f);
            }
            float Pn[NI];
            Pn[0] = 1.f;
            #pragma unroll
            for (int i = 0; i < 15; i++) {
                float gg = s[i];
                float pr = Pn[i] * gg;
                Pn[2 * i + 2] = pr;
                Pn[2 * i + 1] = Pn[i] - pr;
            }
            float a0 = 0.f;
            #pragma unroll
            for (int l = 0; l < 16; l++) {      // leaf pair l, parent node 15+l
                const int p = 15 + l;
                float u = fmaf(s[p], lc[2 * l + 1], lc[2 * l]);
                a0 = fmaf(Pn[p], u, a0);
            }
            oc0 += a0;
            oc1 += c_wt[t] - a0;
        }
    }

    // ---- reduce 2 thread-partials per row (X region reused as scratch) ----
    __syncthreads();
    smf[r * 4 + jhi * 2 + 0] = oc0;
    smf[r * 4 + jhi * 2 + 1] = oc1;
    __syncthreads();
    if (tid < TILE_M) {
        float a0 = smf[tid * 4 + 0] + smf[tid * 4 + 2];
        float a1 = smf[tid * 4 + 1] + smf[tid * 4 + 3];
        int row = m0 + tid;
        if (row < B) ((float2*)out)[row] = make_float2(a0, a1);
    }
}

// ---------------- launch ----------------
extern "C" void kernel_launch(void* const* d_in, const int* in_sizes, int n_in,
                              void* d_out, int out_size)
{
    const float* x  = (const float*)d_in[0];  // [B, 128]
    const float* sw = (const float*)d_in[1];  // [T, 31, 128]
    const float* sb = (const float*)d_in[2];  // [T, 31]
    const float* ll = (const float*)d_in[3];  // [T, 32, 2]
    const float* tw = (const float*)d_in[4];  // [T]
    const float* fm = (const float*)d_in[5];  // [T, 128]

    int T = in_sizes[4];
    if (T > TMAX) T = TMAX;
    int B = in_sizes[0] / F;

    cudaFuncSetAttribute(forest_mma, cudaFuncAttributeMaxDynamicSharedMemorySize, SMEM_BYTES);

    prep<<<(NGROUP * 128 * F + 255) / 256, 256>>>(sw, fm, sb, ll, tw, T);

    void* p = nullptr;
    cudaGetSymbolAddress(&p, g_bs);
    cudaMemcpyToSymbolAsync(c_bs05, p, (size_t)TMAX * 32 * sizeof(float), 0,
                            cudaMemcpyDeviceToDevice, 0);
    cudaGetSymbolAddress(&p, g_lc);
    cudaMemcpyToSymbolAsync(c_lc, p, (size_t)TMAX * 32 * sizeof(float), 0,
                            cudaMemcpyDeviceToDevice, 0);
    cudaGetSymbolAddress(&p, g_wt);
    cudaMemcpyToSymbolAsync(c_wt, p, (size_t)TMAX * sizeof(float), 0,
                            cudaMemcpyDeviceToDevice, 0);

    forest_mma<<<(B + TILE_M - 1) / TILE_M, NTHREADS, SMEM_BYTES>>>(x, (float*)d_out, B);
}

// round 14
// speedup vs baseline: 1.3318x; 1.3318x over previous
#include <cuda_runtime.h>
#include <cuda_fp16.h>
#include <cstdint>

typedef unsigned int u32;
typedef unsigned long long u64;

#define F       128
#define NI      31
#define NL      32
#define TMAX    20
#define NGROUP  5            // 5 groups x 4 trees (128 node-cols per group)
#define TILE_M  128
#define NTHREADS 256

// ---- SMEM layout (bytes) ----
// X/W row stride: 72 u32 words (144 fp16, 288B). 72 mod 32 = 8 -> conflict-free LDS.64.
#define STW72  72
#define X_OFF  0             // 128 rows * 288B = 36864 (reused as reduce scratch at the end)
#define W_OFF  36864         // 128 nrows * 288B = 36864
#define L_OFF  73728         // 128 rows * 20 quads * 16B = 40960 (fp16 SIGMOIDS, quad-swizzled)
#define SMEM_BYTES 114688
// L quad layout: quad = row*20 + tree*4 + (t4 ^ ((row>>1)&3)); quad holds 4 h2 (nt=0..3)

#define H2_HALF 0x38003800u  // fp16x2 {0.5, 0.5}

// __device__ scratch (allocation-free)
__device__ __half g_Wh[NGROUP * 128 * F];  // fp16 HALVED masked weights, k pair-permuted per 16-block
__device__ float  g_bs[TMAX * 32];         // 0.5*bias, padded to 32 nodes
__device__ float  g_lc[TMAX * 32];         // leaf pairs: {base_l, delta_l} for class 0
__device__ float  g_wt[TMAX];              // softmax tree weight

__constant__ float c_bs05[TMAX * 32];
__constant__ float c_lc[TMAX * 32];
__constant__ float c_wt[TMAX];

// ---------------- helpers ----------------
__device__ __forceinline__ u32 smem_u32(const void* p) {
    u32 a;
    asm("{ .reg .u64 t; cvta.to.shared.u64 t, %1; cvt.u32.u64 %0, t; }" : "=r"(a) : "l"(p));
    return a;
}
__device__ __forceinline__ u32 pack_h2(float lo, float hi) {
    u32 r;
    asm("cvt.rn.f16x2.f32 %0, %1, %2;" : "=r"(r) : "f"(hi), "f"(lo));
    return r;
}
// packed sigmoid of half-logit pair: s = 0.5*tanh(l/2) + 0.5 (input is already l/2)
__device__ __forceinline__ u32 sigmoid_h2(u32 hl) {
    u32 th, s;
    asm("tanh.approx.f16x2 %0, %1;" : "=r"(th) : "r"(hl));
    asm("fma.rn.f16x2 %0, %1, %2, %3;" : "=r"(s) : "r"(th), "r"(H2_HALF), "r"(H2_HALF));
    return s;
}
__device__ __forceinline__ void cpa16(u32 dst, const void* src) {
    asm volatile("cp.async.cg.shared.global [%0], [%1], 16;" :: "r"(dst), "l"(src) : "memory");
}
#define CP_COMMIT() asm volatile("cp.async.commit_group;" ::: "memory")
template<int N> __device__ __forceinline__ void cp_wait() {
    asm volatile("cp.async.wait_group %0;" :: "n"(N) : "memory");
}
__device__ __forceinline__ void lds_v2(u32& a, u32& b, u32 addr) {
    asm volatile("ld.shared.v2.u32 {%0,%1}, [%2];" : "=r"(a), "=r"(b) : "r"(addr));
}
__device__ __forceinline__ void lds_v4(u32& a, u32& b, u32& c, u32& d, u32 addr) {
    asm volatile("ld.shared.v4.u32 {%0,%1,%2,%3}, [%4];"
                 : "=r"(a), "=r"(b), "=r"(c), "=r"(d) : "r"(addr));
}
__device__ __forceinline__ void sts_v4(u32 addr, u32 a, u32 b, u32 c, u32 d) {
    asm volatile("st.shared.v4.u32 [%0], {%1,%2,%3,%4};"
                 :: "r"(addr), "r"(a), "r"(b), "r"(c), "r"(d) : "memory");
}

// m16n8k16 f16 MMA, fp32 accum.
#define MMA_F16(c, a0, a1, a2, a3, b0, b1) \
    asm volatile("mma.sync.aligned.m16n8k16.row.col.f32.f16.f16.f32 " \
        "{%0,%1,%2,%3}, {%4,%5,%6,%7}, {%8,%9}, {%0,%1,%2,%3};" \
        : "+f"((c)[0]), "+f"((c)[1]), "+f"((c)[2]), "+f"((c)[3]) \
        : "r"(a0), "r"(a1), "r"(a2), "r"(a3), "r"(b0), "r"(b1))

// ---------------- prologue ----------------
// k-permutation within each 16-k block so a lane's B fragment is one LDS.64.
__global__ void prep(const float* __restrict__ sw, const float* __restrict__ fm,
                     const float* __restrict__ sb,
                     const float* __restrict__ ll, const float* __restrict__ tw, int T) {
    int idx = blockIdx.x * 256 + threadIdx.x;
    const int total = NGROUP * 128 * F;   // 81920
    if (idx < total) {
        int k    = idx & 127;
        int nrow = (idx >> 7) & 127;
        int g    = idx >> 14;
        int t    = g * 4 + (nrow >> 5);
        int n    = nrow & 31;
        float v = 0.f;
        if (t < T && n < NI) v = 0.5f * sw[(t * NI + n) * F + k] * fm[t * F + k];
        int k16 = k & 15;
        int slot = ((k16 & 7) >> 1) * 4 + ((k16 >> 3) & 1) * 2 + (k16 & 1);
        g_Wh[(idx & ~127) + (k & ~15) + slot] = __float2half_rn(v);
    }
    if (idx < TMAX * 32) {   // halved bias, node 31 padded to 0
        int t = idx >> 5, n = idx & 31;
        g_bs[idx] = (t < T && n < NI) ? 0.5f * sb[t * NI + n] : 0.f;
    }
    if (idx < TMAX * 16) {   // leaf lerp constants (class 0)
        int t = idx >> 4, l = idx & 15;
        float base = 0.f, delta = 0.f;
        if (t < T) {
            float m = -1e30f;
            for (int k = 0; k < T; k++) m = fmaxf(m, tw[k]);
            float den = 0.f;
            for (int k = 0; k < T; k++) den += expf(tw[k] - m);
            float w = expf(tw[t] - m) / den;
            float a0 = ll[(t * NL + 2 * l) * 2 + 0], b0 = ll[(t * NL + 2 * l) * 2 + 1];
            float a1 = ll[(t * NL + 2 * l + 1) * 2 + 0], b1 = ll[(t * NL + 2 * l + 1) * 2 + 1];
            float m0 = fmaxf(a0, b0), m1 = fmaxf(a1, b1);
            float e0 = expf(a0 - m0), f0 = expf(b0 - m0);
            float e1 = expf(a1 - m1), f1 = expf(b1 - m1);
            float p0 = w * e0 / (e0 + f0);
            float p1 = w * e1 / (e1 + f1);
            base = p0; delta = p1 - p0;
        }
        g_lc[t * 32 + 2 * l + 0] = base;
        g_lc[t * 32 + 2 * l + 1] = delta;
    }
    if (idx < TMAX) {        // tree weights
        float w = 0.f;
        if (idx < T) {
            float m = -1e30f;
            for (int k = 0; k < T; k++) m = fmaxf(m, tw[k]);
            float den = 0.f;
            for (int k = 0; k < T; k++) den += expf(tw[k] - m);
            w = expf(tw[idx] - m) / den;
        }
        g_wt[idx] = w;
    }
}

// ---------------- main fused kernel ----------------
// R12 structure (best: 100.4us). Change: writer applies packed fp16 sigmoid
// (tanh.approx.f16x2) before STS, so the reader skips tanh+fma entirely.
__global__ void __launch_bounds__(NTHREADS, 2) forest_mma(
    const float* __restrict__ x, float* __restrict__ out, int B)
{
    extern __shared__ char smem[];
    float* smf = (float*)smem;
    const u32 sbase = smem_u32(smem);
    const int tid  = threadIdx.x;
    const int lane = tid & 31;
    const int wid  = tid >> 5;
    const int gid  = lane >> 2;
    const int tid4 = lane & 3;
    const int warp_m = wid & 1;      // 2 M-groups of 64 rows
    const int warp_n = wid >> 1;     // 4 N-groups of 32 cols (= tree-in-group)
    const int m0 = blockIdx.x * TILE_M;

    // ---- cp.async W group 0 ----
    {
        const __half* src = g_Wh;
        #pragma unroll
        for (int j = 0; j < 8; j++) {
            int i = tid + j * NTHREADS;
            int row = i >> 4, c = i & 15;
            cpa16(sbase + W_OFF + (u32)(row * STW72 * 4) + c * 16, src + row * F + c * 8);
        }
        CP_COMMIT();
    }

    // ---- stage X: LDG float4 -> fp16 pairs at permuted slots ----
    {
        #pragma unroll
        for (int j = 0; j < 16; j++) {
            int i = tid + j * NTHREADS;
            int row = i >> 5, c = i & 31;
            int srow = m0 + row; if (srow >= B) srow = B - 1;
            float4 v = ((const float4*)(x + (size_t)srow * F))[c];
            u32 h01 = pack_h2(v.x, v.y);
            u32 h23 = pack_h2(v.z, v.w);
            int kb = c >> 2, jj = c & 3;
            int wbase = (jj & 1) * 4 + (jj >> 1);
            u32 waddr = sbase + X_OFF + (u32)((row * STW72 + kb * 8 + wbase) * 4);
            asm volatile("st.shared.u32 [%0], %1;" :: "r"(waddr), "r"(h01));
            asm volatile("st.shared.u32 [%0], %1;" :: "r"(waddr + 8), "r"(h23));
        }
    }

    // fragment bases
    const u32 Abase = sbase + X_OFF + (u32)(((warp_m * 64 + gid) * STW72 + tid4 * 2) * 4);
    const u32 Bbase = sbase + W_OFF + (u32)(((warp_n * 32 + gid) * STW72 + tid4 * 2) * 4);

    // reader identity: row r, tree pair
    const int r    = tid & 127;
    const int jhi  = tid >> 7;             // 0/1 -> trees {0,1} or {2,3} of group
    const int sr   = (r >> 1) & 3;         // quad swizzle key for this row
    const u32 Rrow = sbase + L_OFF + (u32)(r * 20 * 16);

    float oc0 = 0.f, oc1 = 0.f;

    #pragma unroll 1
    for (int g = 0; g < NGROUP; g++) {
        cp_wait<0>();
        __syncthreads();             // W(g) (+X on g=0) visible; L(g-1) reads done

        // ================= GEMM(g): acc starts at 0.5*bias =================
        float acc[4][4][4];
        {
            const float* bsp = c_bs05 + ((g * 4 + warp_n) * 32 + tid4 * 2);
            #pragma unroll
            for (int nt = 0; nt < 4; nt++) {
                float b0 = bsp[nt * 8], b1 = bsp[nt * 8 + 1];
                #pragma unroll
                for (int mt = 0; mt < 4; mt++) {
                    acc[mt][nt][0] = b0; acc[mt][nt][1] = b1;
                    acc[mt][nt][2] = b0; acc[mt][nt][3] = b1;
                }
            }
        }

        #pragma unroll
        for (int kk = 0; kk < 8; kk++) {
            u32 a[4][4];
            #pragma unroll
            for (int mt = 0; mt < 4; mt++) {
                const u32 r0 = Abase + (u32)((mt * 16 * STW72 + kk * 8) * 4);
                lds_v2(a[mt][0], a[mt][2], r0);
                lds_v2(a[mt][1], a[mt][3], r0 + 8 * STW72 * 4);
            }
            #pragma unroll
            for (int nt = 0; nt < 4; nt++) {
                u32 b0, b1;
                lds_v2(b0, b1, Bbase + (u32)((nt * 8 * STW72 + kk * 8) * 4));
                #pragma unroll
                for (int mt = 0; mt < 4; mt++)
                    MMA_F16(acc[mt][nt], a[mt][0], a[mt][1], a[mt][2], a[mt][3], b0, b1);
            }
        }

        __syncthreads();             // W(g) reads complete -> buffer free

        // prefetch W(g+1) (overlaps sigmoid store + epilogue)
        if (g < NGROUP - 1) {
            const __half* src = g_Wh + (size_t)(g + 1) * 128 * F;
            #pragma unroll
            for (int j = 0; j < 8; j++) {
                int i = tid + j * NTHREADS;
                int row = i >> 4, c = i & 15;
                cpa16(sbase + W_OFF + (u32)(row * STW72 * 4) + c * 16, src + row * F + c * 8);
            }
            CP_COMMIT();
        }

        // ---- pack + SIGMOID in fp16x2, STS.128 (8 per thread, conflict-free) ----
        #pragma unroll
        for (int mt = 0; mt < 4; mt++) {
            #pragma unroll
            for (int half = 0; half < 2; half++) {
                const int row = warp_m * 64 + mt * 16 + half * 8 + gid;
                u32 h0 = sigmoid_h2(pack_h2(acc[mt][0][2 * half], acc[mt][0][2 * half + 1]));
                u32 h1 = sigmoid_h2(pack_h2(acc[mt][1][2 * half], acc[mt][1][2 * half + 1]));
                u32 h2 = sigmoid_h2(pack_h2(acc[mt][2][2 * half], acc[mt][2][2 * half + 1]));
                u32 h3 = sigmoid_h2(pack_h2(acc[mt][3][2 * half], acc[mt][3][2 * half + 1]));
                u32 quad = (u32)(row * 20 + warp_n * 4 + (tid4 ^ ((row >> 1) & 3)));
                sts_v4(sbase + L_OFF + quad * 16, h0, h1, h2, h3);
            }
        }
        __syncthreads();             // sigmoids(g) visible

        // ---- epilogue: 2 (row, tree) tasks per thread ----
        #pragma unroll
        for (int j2 = 0; j2 < 2; j2++) {
            const int tp = jhi * 2 + j2;        // tree-in-group 0..3
            const int t  = g * 4 + tp;
            const float* lc = c_lc + t * 32;
            float s[32];
            #pragma unroll
            for (int q = 0; q < 4; q++) {       // logical quad = writer's tid4
                u32 w0, w1, w2, w3;
                lds_v4(w0, w1, w2, w3, Rrow + (u32)(tp * 4 + (q ^ sr)) * 16);
                const u32 ws[4] = {w0, w1, w2, w3};
                #pragma unroll
                for (int nt = 0; nt < 4; nt++) {
                    __half2 hv = *(__half2*)&ws[nt];
                    const int n = nt * 8 + 2 * q;
                    s[n]     = __low2float(hv);     // already sigmoid
                    s[n + 1] = __high2float(hv);
                }
            }
            float Pn[NI];
            Pn[0] = 1.f;
            #pragma unroll
            for (int i = 0; i < 15; i++) {
                float gg = s[i];
                float pr = Pn[i] * gg;
                Pn[2 * i + 2] = pr;
                Pn[2 * i + 1] = Pn[i] - pr;
            }
            float a0 = 0.f;
            #pragma unroll
            for (int l = 0; l < 16; l++) {      // leaf pair l, parent node 15+l
                const int p = 15 + l;
                float u = fmaf(s[p], lc[2 * l + 1], lc[2 * l]);
                a0 = fmaf(Pn[p], u, a0);
            }
            oc0 += a0;
            oc1 += c_wt[t] - a0;
        }
    }

    // ---- reduce 2 thread-partials per row (X region reused as scratch) ----
    __syncthreads();
    smf[r * 4 + jhi * 2 + 0] = oc0;
    smf[r * 4 + jhi * 2 + 1] = oc1;
    __syncthreads();
    if (tid < TILE_M) {
        float a0 = smf[tid * 4 + 0] + smf[tid * 4 + 2];
        float a1 = smf[tid * 4 + 1] + smf[tid * 4 + 3];
        int row = m0 + tid;
        if (row < B) ((float2*)out)[row] = make_float2(a0, a1);
    }
}

// ---------------- launch ----------------
extern "C" void kernel_launch(void* const* d_in, const int* in_sizes, int n_in,
                              void* d_out, int out_size)
{
    const float* x  = (const float*)d_in[0];  // [B, 128]
    const float* sw = (const float*)d_in[1];  // [T, 31, 128]
    const float* sb = (const float*)d_in[2];  // [T, 31]
    const float* ll = (const float*)d_in[3];  // [T, 32, 2]
    const float* tw = (const float*)d_in[4];  // [T]
    const float* fm = (const float*)d_in[5];  // [T, 128]

    int T = in_sizes[4];
    if (T > TMAX) T = TMAX;
    int B = in_sizes[0] / F;

    cudaFuncSetAttribute(forest_mma, cudaFuncAttributeMaxDynamicSharedMemorySize, SMEM_BYTES);

    prep<<<(NGROUP * 128 * F + 255) / 256, 256>>>(sw, fm, sb, ll, tw, T);

    void* p = nullptr;
    cudaGetSymbolAddress(&p, g_bs);
    cudaMemcpyToSymbolAsync(c_bs05, p, (size_t)TMAX * 32 * sizeof(float), 0,
                            cudaMemcpyDeviceToDevice, 0);
    cudaGetSymbolAddress(&p, g_lc);
    cudaMemcpyToSymbolAsync(c_lc, p, (size_t)TMAX * 32 * sizeof(float), 0,
                            cudaMemcpyDeviceToDevice, 0);
    cudaGetSymbolAddress(&p, g_wt);
    cudaMemcpyToSymbolAsync(c_wt, p, (size_t)TMAX * sizeof(float), 0,
                            cudaMemcpyDeviceToDevice, 0);

    forest_mma<<<(B + TILE_M - 1) / TILE_M, NTHREADS, SMEM_BYTES>>>(x, (float*)d_out, B);
}

// round 15
// speedup vs baseline: 1.5282x; 1.1475x over previous
#include <cuda_runtime.h>
#include <cuda_fp16.h>
#include <cstdint>

typedef unsigned int u32;
typedef unsigned long long u64;

#define F       128
#define NI      31
#define NL      32
#define TMAX    20
#define NGROUP  5            // 5 groups x 4 trees (128 node-cols per group)
#define TILE_M  128
#define NTHREADS 256

// ---- SMEM layout (bytes) ----
// X/W row stride: 72 u32 words (144 fp16, 288B). 72 mod 32 = 8 -> conflict-free LDS.64.
#define STW72  72
#define X_OFF  0             // 128 rows * 288B = 36864 (reused as reduce scratch at the end)
#define W_OFF  36864         // 128 nrows * 288B = 36864
#define L_OFF  73728         // 128 rows * 20 quads * 16B = 40960 (fp16 half-logits, quad-swizzled)
#define SMEM_BYTES 114688
// L quad layout: quad = row*20 + tree*4 + (t4 ^ ((row>>1)&3)); quad holds 4 h2 (nt=0..3)

// __device__ scratch (allocation-free)
__device__ __half g_Wh[NGROUP * 128 * F];  // fp16 HALVED masked weights, k pair-permuted per 16-block
__device__ float  g_bs[TMAX * 32];         // 0.5*bias, padded to 32 nodes
__device__ float  g_lc[TMAX * 32];         // leaf pairs: {base_l, delta_l} for class 0
__device__ float  g_wt[TMAX];              // softmax tree weight

__constant__ float c_bs05[TMAX * 32];
__constant__ float c_lc[TMAX * 32];
__constant__ float c_wt[TMAX];

// ---------------- helpers ----------------
__device__ __forceinline__ u32 smem_u32(const void* p) {
    u32 a;
    asm("{ .reg .u64 t; cvta.to.shared.u64 t, %1; cvt.u32.u64 %0, t; }" : "=r"(a) : "l"(p));
    return a;
}
__device__ __forceinline__ u32 pack_h2(float lo, float hi) {
    u32 r;
    asm("cvt.rn.f16x2.f32 %0, %1, %2;" : "=r"(r) : "f"(hi), "f"(lo));
    return r;
}
__device__ __forceinline__ void cpa16(u32 dst, const void* src) {
    asm volatile("cp.async.cg.shared.global [%0], [%1], 16;" :: "r"(dst), "l"(src) : "memory");
}
#define CP_COMMIT() asm volatile("cp.async.commit_group;" ::: "memory")
template<int N> __device__ __forceinline__ void cp_wait() {
    asm volatile("cp.async.wait_group %0;" :: "n"(N) : "memory");
}
__device__ __forceinline__ void lds_v2(u32& a, u32& b, u32 addr) {
    asm volatile("ld.shared.v2.u32 {%0,%1}, [%2];" : "=r"(a), "=r"(b) : "r"(addr));
}
__device__ __forceinline__ void lds_v4(u32& a, u32& b, u32& c, u32& d, u32 addr) {
    asm volatile("ld.shared.v4.u32 {%0,%1,%2,%3}, [%4];"
                 : "=r"(a), "=r"(b), "=r"(c), "=r"(d) : "r"(addr));
}
__device__ __forceinline__ void sts_v4(u32 addr, u32 a, u32 b, u32 c, u32 d) {
    asm volatile("st.shared.v4.u32 [%0], {%1,%2,%3,%4};"
                 :: "r"(addr), "r"(a), "r"(b), "r"(c), "r"(d) : "memory");
}

// m16n8k16 f16 MMA, fp32 accum.
#define MMA_F16(c, a0, a1, a2, a3, b0, b1) \
    asm volatile("mma.sync.aligned.m16n8k16.row.col.f32.f16.f16.f32 " \
        "{%0,%1,%2,%3}, {%4,%5,%6,%7}, {%8,%9}, {%0,%1,%2,%3};" \
        : "+f"((c)[0]), "+f"((c)[1]), "+f"((c)[2]), "+f"((c)[3]) \
        : "r"(a0), "r"(a1), "r"(a2), "r"(a3), "r"(b0), "r"(b1))

// ---------------- prologue ----------------
// k-permutation within each 16-k block so a lane's B fragment is one LDS.64.
__global__ void prep(const float* __restrict__ sw, const float* __restrict__ fm,
                     const float* __restrict__ sb,
                     const float* __restrict__ ll, const float* __restrict__ tw, int T) {
    int idx = blockIdx.x * 256 + threadIdx.x;
    const int total = NGROUP * 128 * F;   // 81920
    if (idx < total) {
        int k    = idx & 127;
        int nrow = (idx >> 7) & 127;
        int g    = idx >> 14;
        int t    = g * 4 + (nrow >> 5);
        int n    = nrow & 31;
        float v = 0.f;
        if (t < T && n < NI) v = 0.5f * sw[(t * NI + n) * F + k] * fm[t * F + k];
        int k16 = k & 15;
        int slot = ((k16 & 7) >> 1) * 4 + ((k16 >> 3) & 1) * 2 + (k16 & 1);
        g_Wh[(idx & ~127) + (k & ~15) + slot] = __float2half_rn(v);
    }
    if (idx < TMAX * 32) {   // halved bias, node 31 padded to 0
        int t = idx >> 5, n = idx & 31;
        g_bs[idx] = (t < T && n < NI) ? 0.5f * sb[t * NI + n] : 0.f;
    }
    if (idx < TMAX * 16) {   // leaf lerp constants (class 0)
        int t = idx >> 4, l = idx & 15;
        float base = 0.f, delta = 0.f;
        if (t < T) {
            float m = -1e30f;
            for (int k = 0; k < T; k++) m = fmaxf(m, tw[k]);
            float den = 0.f;
            for (int k = 0; k < T; k++) den += expf(tw[k] - m);
            float w = expf(tw[t] - m) / den;
            float a0 = ll[(t * NL + 2 * l) * 2 + 0], b0 = ll[(t * NL + 2 * l) * 2 + 1];
            float a1 = ll[(t * NL + 2 * l + 1) * 2 + 0], b1 = ll[(t * NL + 2 * l + 1) * 2 + 1];
            float m0 = fmaxf(a0, b0), m1 = fmaxf(a1, b1);
            float e0 = expf(a0 - m0), f0 = expf(b0 - m0);
            float e1 = expf(a1 - m1), f1 = expf(b1 - m1);
            float p0 = w * e0 / (e0 + f0);
            float p1 = w * e1 / (e1 + f1);
            base = p0; delta = p1 - p0;
        }
        g_lc[t * 32 + 2 * l + 0] = base;
        g_lc[t * 32 + 2 * l + 1] = delta;
    }
    if (idx < TMAX) {        // tree weights
        float w = 0.f;
        if (idx < T) {
            float m = -1e30f;
            for (int k = 0; k < T; k++) m = fmaxf(m, tw[k]);
            float den = 0.f;
            for (int k = 0; k < T; k++) den += expf(tw[k] - m);
            w = expf(tw[idx] - m) / den;
        }
        g_wt[idx] = w;
    }
}

// ---------------- main fused kernel ----------------
// R12 structure with barriers merged 3->2 per group:
//   [GEMM] [pack+STS L] sync{W free + L visible} [cp.async W(g+1)] [epilogue] -> loop-top sync
__global__ void __launch_bounds__(NTHREADS, 2) forest_mma(
    const float* __restrict__ x, float* __restrict__ out, int B)
{
    extern __shared__ char smem[];
    float* smf = (float*)smem;
    const u32 sbase = smem_u32(smem);
    const int tid  = threadIdx.x;
    const int lane = tid & 31;
    const int wid  = tid >> 5;
    const int gid  = lane >> 2;
    const int tid4 = lane & 3;
    const int warp_m = wid & 1;      // 2 M-groups of 64 rows
    const int warp_n = wid >> 1;     // 4 N-groups of 32 cols (= tree-in-group)
    const int m0 = blockIdx.x * TILE_M;

    // ---- cp.async W group 0 ----
    {
        const __half* src = g_Wh;
        #pragma unroll
        for (int j = 0; j < 8; j++) {
            int i = tid + j * NTHREADS;
            int row = i >> 4, c = i & 15;
            cpa16(sbase + W_OFF + (u32)(row * STW72 * 4) + c * 16, src + row * F + c * 8);
        }
        CP_COMMIT();
    }

    // ---- stage X: LDG float4 -> fp16 pairs at permuted slots ----
    {
        #pragma unroll
        for (int j = 0; j < 16; j++) {
            int i = tid + j * NTHREADS;
            int row = i >> 5, c = i & 31;
            int srow = m0 + row; if (srow >= B) srow = B - 1;
            float4 v = ((const float4*)(x + (size_t)srow * F))[c];
            u32 h01 = pack_h2(v.x, v.y);
            u32 h23 = pack_h2(v.z, v.w);
            int kb = c >> 2, jj = c & 3;
            int wbase = (jj & 1) * 4 + (jj >> 1);
            u32 waddr = sbase + X_OFF + (u32)((row * STW72 + kb * 8 + wbase) * 4);
            asm volatile("st.shared.u32 [%0], %1;" :: "r"(waddr), "r"(h01));
            asm volatile("st.shared.u32 [%0], %1;" :: "r"(waddr + 8), "r"(h23));
        }
    }

    // fragment bases
    const u32 Abase = sbase + X_OFF + (u32)(((warp_m * 64 + gid) * STW72 + tid4 * 2) * 4);
    const u32 Bbase = sbase + W_OFF + (u32)(((warp_n * 32 + gid) * STW72 + tid4 * 2) * 4);

    // reader identity: row r, tree pair
    const int r    = tid & 127;
    const int jhi  = tid >> 7;             // 0/1 -> trees {0,1} or {2,3} of group
    const int sr   = (r >> 1) & 3;         // quad swizzle key for this row
    const u32 Rrow = sbase + L_OFF + (u32)(r * 20 * 16);

    float oc0 = 0.f, oc1 = 0.f;

    #pragma unroll 1
    for (int g = 0; g < NGROUP; g++) {
        cp_wait<0>();
        __syncthreads();             // W(g) (+X on g=0) visible; epilogue(g-1) L-reads done

        // ================= GEMM(g): acc starts at 0.5*bias =================
        float acc[4][4][4];
        {
            const float* bsp = c_bs05 + ((g * 4 + warp_n) * 32 + tid4 * 2);
            #pragma unroll
            for (int nt = 0; nt < 4; nt++) {
                float b0 = bsp[nt * 8], b1 = bsp[nt * 8 + 1];
                #pragma unroll
                for (int mt = 0; mt < 4; mt++) {
                    acc[mt][nt][0] = b0; acc[mt][nt][1] = b1;
                    acc[mt][nt][2] = b0; acc[mt][nt][3] = b1;
                }
            }
        }

        #pragma unroll
        for (int kk = 0; kk < 8; kk++) {
            u32 a[4][4];
            #pragma unroll
            for (int mt = 0; mt < 4; mt++) {
                const u32 r0 = Abase + (u32)((mt * 16 * STW72 + kk * 8) * 4);
                lds_v2(a[mt][0], a[mt][2], r0);
                lds_v2(a[mt][1], a[mt][3], r0 + 8 * STW72 * 4);
            }
            #pragma unroll
            for (int nt = 0; nt < 4; nt++) {
                u32 b0, b1;
                lds_v2(b0, b1, Bbase + (u32)((nt * 8 * STW72 + kk * 8) * 4));
                #pragma unroll
                for (int mt = 0; mt < 4; mt++)
                    MMA_F16(acc[mt][nt], a[mt][0], a[mt][1], a[mt][2], a[mt][3], b0, b1);
            }
        }

        // ---- pack fp16 half-logits, STS.128 (before the merged barrier) ----
        #pragma unroll
        for (int mt = 0; mt < 4; mt++) {
            #pragma unroll
            for (int half = 0; half < 2; half++) {
                const int row = warp_m * 64 + mt * 16 + half * 8 + gid;
                u32 h0 = pack_h2(acc[mt][0][2 * half], acc[mt][0][2 * half + 1]);
                u32 h1 = pack_h2(acc[mt][1][2 * half], acc[mt][1][2 * half + 1]);
                u32 h2 = pack_h2(acc[mt][2][2 * half], acc[mt][2][2 * half + 1]);
                u32 h3 = pack_h2(acc[mt][3][2 * half], acc[mt][3][2 * half + 1]);
                u32 quad = (u32)(row * 20 + warp_n * 4 + (tid4 ^ ((row >> 1) & 3)));
                sts_v4(sbase + L_OFF + quad * 16, h0, h1, h2, h3);
            }
        }

        __syncthreads();             // merged: W(g) reads done (buffer free) + L(g) visible

        // prefetch W(g+1) (overlaps epilogue)
        if (g < NGROUP - 1) {
            const __half* src = g_Wh + (size_t)(g + 1) * 128 * F;
            #pragma unroll
            for (int j = 0; j < 8; j++) {
                int i = tid + j * NTHREADS;
                int row = i >> 4, c = i & 15;
                cpa16(sbase + W_OFF + (u32)(row * STW72 * 4) + c * 16, src + row * F + c * 8);
            }
            CP_COMMIT();
        }

        // ---- epilogue: 2 (row, tree) tasks per thread ----
        #pragma unroll
        for (int j2 = 0; j2 < 2; j2++) {
            const int tp = jhi * 2 + j2;        // tree-in-group 0..3
            const int t  = g * 4 + tp;
            const float* lc = c_lc + t * 32;
            float s[32];
            #pragma unroll
            for (int q = 0; q < 4; q++) {       // logical quad = writer's tid4
                u32 w0, w1, w2, w3;
                lds_v4(w0, w1, w2, w3, Rrow + (u32)(tp * 4 + (q ^ sr)) * 16);
                const u32 ws[4] = {w0, w1, w2, w3};
                #pragma unroll
                for (int nt = 0; nt < 4; nt++) {
                    __half2 hv = *(__half2*)&ws[nt];
                    const int n = nt * 8 + 2 * q;
                    s[n]     = __low2float(hv);
                    s[n + 1] = __high2float(hv);
                }
            }
            // values are l/2 -> sigmoid = 0.5*tanh + 0.5
            #pragma unroll
            for (int n = 0; n < NI; n++) {
                float th;
                asm("tanh.approx.f32 %0, %1;" : "=f"(th) : "f"(s[n]));
                s[n] = fmaf(0.5f, th, 0.5f);
            }
            float Pn[NI];
            Pn[0] = 1.f;
            #pragma unroll
            for (int i = 0; i < 15; i++) {
                float gg = s[i];
                float pr = Pn[i] * gg;
                Pn[2 * i + 2] = pr;
                Pn[2 * i + 1] = Pn[i] - pr;
            }
            float a0 = 0.f;
            #pragma unroll
            for (int l = 0; l < 16; l++) {      // leaf pair l, parent node 15+l
                const int p = 15 + l;
                float u = fmaf(s[p], lc[2 * l + 1], lc[2 * l]);
                a0 = fmaf(Pn[p], u, a0);
            }
            oc0 += a0;
            oc1 += c_wt[t] - a0;
        }
    }

    // ---- reduce 2 thread-partials per row (X region reused as scratch) ----
    __syncthreads();
    smf[r * 4 + jhi * 2 + 0] = oc0;
    smf[r * 4 + jhi * 2 + 1] = oc1;
    __syncthreads();
    if (tid < TILE_M) {
        float a0 = smf[tid * 4 + 0] + smf[tid * 4 + 2];
        float a1 = smf[tid * 4 + 1] + smf[tid * 4 + 3];
        int row = m0 + tid;
        if (row < B) ((float2*)out)[row] = make_float2(a0, a1);
    }
}

// ---------------- launch ----------------
extern "C" void kernel_launch(void* const* d_in, const int* in_sizes, int n_in,
                              void* d_out, int out_size)
{
    const float* x  = (const float*)d_in[0];  // [B, 128]
    const float* sw = (const float*)d_in[1];  // [T, 31, 128]
    const float* sb = (const float*)d_in[2];  // [T, 31]
    const float* ll = (const float*)d_in[3];  // [T, 32, 2]
    const float* tw = (const float*)d_in[4];  // [T]
    const float* fm = (const float*)d_in[5];  // [T, 128]

    int T = in_sizes[4];
    if (T > TMAX) T = TMAX;
    int B = in_sizes[0] / F;

    cudaFuncSetAttribute(forest_mma, cudaFuncAttributeMaxDynamicSharedMemorySize, SMEM_BYTES);

    prep<<<(NGROUP * 128 * F + 255) / 256, 256>>>(sw, fm, sb, ll, tw, T);

    void* p = nullptr;
    cudaGetSymbolAddress(&p, g_bs);
    cudaMemcpyToSymbolAsync(c_bs05, p, (size_t)TMAX * 32 * sizeof(float), 0,
                            cudaMemcpyDeviceToDevice, 0);
    cudaGetSymbolAddress(&p, g_lc);
    cudaMemcpyToSymbolAsync(c_lc, p, (size_t)TMAX * 32 * sizeof(float), 0,
                            cudaMemcpyDeviceToDevice, 0);
    cudaGetSymbolAddress(&p, g_wt);
    cudaMemcpyToSymbolAsync(c_wt, p, (size_t)TMAX * sizeof(float), 0,
                            cudaMemcpyDeviceToDevice, 0);

    forest_mma<<<(B + TILE_M - 1) / TILE_M, NTHREADS, SMEM_BYTES>>>(x, (float*)d_out, B);
}

// round 16
// speedup vs baseline: 1.5994x; 1.0466x over previous
#include <cuda_runtime.h>
#include <cuda_fp16.h>
#include <cstdint>

typedef unsigned int u32;
typedef unsigned long long u64;

#define F       128
#define NI      31
#define NL      32
#define TMAX    20
#define NGROUP  5            // 5 groups x 4 trees (128 node-cols per group)
#define TILE_M  128
#define NTHREADS 256

// ---- SMEM layout (bytes) ----
// X/W row stride: 72 u32 words (144 fp16, 288B). 72 mod 32 = 8 -> conflict-free LDS.64.
#define STW72  72
#define X_OFF  0             // 128 rows * 288B = 36864 (reused as reduce scratch at the end)
#define W_OFF  36864         // 128 nrows * 288B = 36864
#define L_OFF  73728         // 128 rows * 20 quads * 16B = 40960 (fp16 half-logits, quad-swizzled)
#define SMEM_BYTES 114688
// L quad layout: quad = row*20 + tree*4 + (t4 ^ ((row>>1)&3)); quad holds 4 h2 (nt=0..3)

// __device__ scratch (allocation-free)
__device__ __half g_Wh[NGROUP * 128 * F];  // fp16 HALVED masked weights, k pair-permuted per 16-block

struct alignas(16) ConstBlk {
    float bs[TMAX * 32];     // 0.5*bias, padded to 32 nodes
    float lc[TMAX * 32];     // leaf pairs: {base_l, delta_l} for class 0
    float wt[TMAX];          // softmax tree weight
};
__device__   ConstBlk g_cb;  // staging (written by prep)
__constant__ ConstBlk c_cb;  // read by main kernel

// ---------------- helpers ----------------
__device__ __forceinline__ u32 smem_u32(const void* p) {
    u32 a;
    asm("{ .reg .u64 t; cvta.to.shared.u64 t, %1; cvt.u32.u64 %0, t; }" : "=r"(a) : "l"(p));
    return a;
}
__device__ __forceinline__ u32 pack_h2(float lo, float hi) {
    u32 r;
    asm("cvt.rn.f16x2.f32 %0, %1, %2;" : "=r"(r) : "f"(hi), "f"(lo));
    return r;
}
__device__ __forceinline__ void cpa16(u32 dst, const void* src) {
    asm volatile("cp.async.cg.shared.global [%0], [%1], 16;" :: "r"(dst), "l"(src) : "memory");
}
#define CP_COMMIT() asm volatile("cp.async.commit_group;" ::: "memory")
template<int N> __device__ __forceinline__ void cp_wait() {
    asm volatile("cp.async.wait_group %0;" :: "n"(N) : "memory");
}
__device__ __forceinline__ void lds_v2(u32& a, u32& b, u32 addr) {
    asm volatile("ld.shared.v2.u32 {%0,%1}, [%2];" : "=r"(a), "=r"(b) : "r"(addr));
}
__device__ __forceinline__ void lds_v4(u32& a, u32& b, u32& c, u32& d, u32 addr) {
    asm volatile("ld.shared.v4.u32 {%0,%1,%2,%3}, [%4];"
                 : "=r"(a), "=r"(b), "=r"(c), "=r"(d) : "r"(addr));
}
__device__ __forceinline__ void sts_v4(u32 addr, u32 a, u32 b, u32 c, u32 d) {
    asm volatile("st.shared.v4.u32 [%0], {%1,%2,%3,%4};"
                 :: "r"(addr), "r"(a), "r"(b), "r"(c), "r"(d) : "memory");
}

// m16n8k16 f16 MMA, fp32 accum.
#define MMA_F16(c, a0, a1, a2, a3, b0, b1) \
    asm volatile("mma.sync.aligned.m16n8k16.row.col.f32.f16.f16.f32 " \
        "{%0,%1,%2,%3}, {%4,%5,%6,%7}, {%8,%9}, {%0,%1,%2,%3};" \
        : "+f"((c)[0]), "+f"((c)[1]), "+f"((c)[2]), "+f"((c)[3]) \
        : "r"(a0), "r"(a1), "r"(a2), "r"(a3), "r"(b0), "r"(b1))

// ---------------- prologue ----------------
// Weights: 4 consecutive k per thread via float4; k-permutation within each
// 16-k block so a lane's B fragment is one LDS.64. For k=4c..4c+3 the permuted
// slots are pairs {s, s+1} and {s+4, s+5} -> two u32 stores.
__global__ void prep(const float* __restrict__ sw, const float* __restrict__ fm,
                     const float* __restrict__ sb,
                     const float* __restrict__ ll, const float* __restrict__ tw, int T) {
    int idx = blockIdx.x * 256 + threadIdx.x;
    const int totalv = NGROUP * 128 * 32;   // 20480 float4 chunks
    if (idx < totalv) {
        int c    = idx & 31;                // float4 index within row (k = 4c..4c+3)
        int nrow = (idx >> 5) & 127;
        int g    = idx >> 12;
        int t    = g * 4 + (nrow >> 5);
        int n    = nrow & 31;
        float4 v = make_float4(0.f, 0.f, 0.f, 0.f);
        if (t < T && n < NI) {
            float4 w4 = ((const float4*)(sw + (size_t)(t * NI + n) * F))[c];
            float4 m4 = ((const float4*)(fm + (size_t)t * F))[c];
            v.x = 0.5f * w4.x * m4.x;  v.y = 0.5f * w4.y * m4.y;
            v.z = 0.5f * w4.z * m4.z;  v.w = 0.5f * w4.w * m4.w;
        }
        u32 h01 = pack_h2(v.x, v.y);
        u32 h23 = pack_h2(v.z, v.w);
        // slot within 16-block for k16 = 4*(c&3)+j: pairs land at base, base+1 (j=0,1)
        // and base+4, base+5 (j=2,3) where base = ((4c&7)>>1)*4 + ((4c>>3)&1)*2
        int k16c = (c & 3) * 4;
        int base = ((k16c & 7) >> 1) * 4 + ((k16c >> 3) & 1) * 2;
        u32* dst = (u32*)(g_Wh + (size_t)(g * 128 + nrow) * F + (c >> 2) * 16);
        dst[base >> 1]       = h01;
        dst[(base >> 1) + 2] = h23;
    }
    if (idx < TMAX * 32) {   // halved bias, node 31 padded to 0
        int t = idx >> 5, n = idx & 31;
        g_cb.bs[idx] = (t < T && n < NI) ? 0.5f * sb[t * NI + n] : 0.f;
    }
    if (idx < TMAX * 16) {   // leaf lerp constants (class 0)
        int t = idx >> 4, l = idx & 15;
        float base = 0.f, delta = 0.f;
        if (t < T) {
            float m = -1e30f;
            for (int k = 0; k < T; k++) m = fmaxf(m, tw[k]);
            float den = 0.f;
            for (int k = 0; k < T; k++) den += expf(tw[k] - m);
            float w = expf(tw[t] - m) / den;
            float a0 = ll[(t * NL + 2 * l) * 2 + 0], b0 = ll[(t * NL + 2 * l) * 2 + 1];
            float a1 = ll[(t * NL + 2 * l + 1) * 2 + 0], b1 = ll[(t * NL + 2 * l + 1) * 2 + 1];
            float m0 = fmaxf(a0, b0), m1 = fmaxf(a1, b1);
            float e0 = expf(a0 - m0), f0 = expf(b0 - m0);
            float e1 = expf(a1 - m1), f1 = expf(b1 - m1);
            float p0 = w * e0 / (e0 + f0);
            float p1 = w * e1 / (e1 + f1);
            base = p0; delta = p1 - p0;
        }
        g_cb.lc[t * 32 + 2 * l + 0] = base;
        g_cb.lc[t * 32 + 2 * l + 1] = delta;
    }
    if (idx < TMAX) {        // tree weights
        float w = 0.f;
        if (idx < T) {
            float m = -1e30f;
            for (int k = 0; k < T; k++) m = fmaxf(m, tw[k]);
            float den = 0.f;
            for (int k = 0; k < T; k++) den += expf(tw[k] - m);
            w = expf(tw[idx] - m) / den;
        }
        g_cb.wt[idx] = w;
    }
}

// ---------------- main fused kernel (R15, proven 91.2us) ----------------
//   [GEMM] [pack+STS L] sync{W free + L visible} [cp.async W(g+1)] [epilogue] -> loop-top sync
__global__ void __launch_bounds__(NTHREADS, 2) forest_mma(
    const float* __restrict__ x, float* __restrict__ out, int B)
{
    extern __shared__ char smem[];
    float* smf = (float*)smem;
    const u32 sbase = smem_u32(smem);
    const int tid  = threadIdx.x;
    const int lane = tid & 31;
    const int wid  = tid >> 5;
    const int gid  = lane >> 2;
    const int tid4 = lane & 3;
    const int warp_m = wid & 1;      // 2 M-groups of 64 rows
    const int warp_n = wid >> 1;     // 4 N-groups of 32 cols (= tree-in-group)
    const int m0 = blockIdx.x * TILE_M;

    // ---- cp.async W group 0 ----
    {
        const __half* src = g_Wh;
        #pragma unroll
        for (int j = 0; j < 8; j++) {
            int i = tid + j * NTHREADS;
            int row = i >> 4, c = i & 15;
            cpa16(sbase + W_OFF + (u32)(row * STW72 * 4) + c * 16, src + row * F + c * 8);
        }
        CP_COMMIT();
    }

    // ---- stage X: LDG float4 -> fp16 pairs at permuted slots ----
    {
        #pragma unroll
        for (int j = 0; j < 16; j++) {
            int i = tid + j * NTHREADS;
            int row = i >> 5, c = i & 31;
            int srow = m0 + row; if (srow >= B) srow = B - 1;
            float4 v = ((const float4*)(x + (size_t)srow * F))[c];
            u32 h01 = pack_h2(v.x, v.y);
            u32 h23 = pack_h2(v.z, v.w);
            int kb = c >> 2, jj = c & 3;
            int wbase = (jj & 1) * 4 + (jj >> 1);
            u32 waddr = sbase + X_OFF + (u32)((row * STW72 + kb * 8 + wbase) * 4);
            asm volatile("st.shared.u32 [%0], %1;" :: "r"(waddr), "r"(h01));
            asm volatile("st.shared.u32 [%0], %1;" :: "r"(waddr + 8), "r"(h23));
        }
    }

    // fragment bases
    const u32 Abase = sbase + X_OFF + (u32)(((warp_m * 64 + gid) * STW72 + tid4 * 2) * 4);
    const u32 Bbase = sbase + W_OFF + (u32)(((warp_n * 32 + gid) * STW72 + tid4 * 2) * 4);

    // reader identity: row r, tree pair
    const int r    = tid & 127;
    const int jhi  = tid >> 7;             // 0/1 -> trees {0,1} or {2,3} of group
    const int sr   = (r >> 1) & 3;         // quad swizzle key for this row
    const u32 Rrow = sbase + L_OFF + (u32)(r * 20 * 16);

    float oc0 = 0.f, oc1 = 0.f;

    #pragma unroll 1
    for (int g = 0; g < NGROUP; g++) {
        cp_wait<0>();
        __syncthreads();             // W(g) (+X on g=0) visible; epilogue(g-1) L-reads done

        // ================= GEMM(g): acc starts at 0.5*bias =================
        float acc[4][4][4];
        {
            const float* bsp = c_cb.bs + ((g * 4 + warp_n) * 32 + tid4 * 2);
            #pragma unroll
            for (int nt = 0; nt < 4; nt++) {
                float b0 = bsp[nt * 8], b1 = bsp[nt * 8 + 1];
                #pragma unroll
                for (int mt = 0; mt < 4; mt++) {
                    acc[mt][nt][0] = b0; acc[mt][nt][1] = b1;
                    acc[mt][nt][2] = b0; acc[mt][nt][3] = b1;
                }
            }
        }

        #pragma unroll
        for (int kk = 0; kk < 8; kk++) {
            u32 a[4][4];
            #pragma unroll
            for (int mt = 0; mt < 4; mt++) {
                const u32 r0 = Abase + (u32)((mt * 16 * STW72 + kk * 8) * 4);
                lds_v2(a[mt][0], a[mt][2], r0);
                lds_v2(a[mt][1], a[mt][3], r0 + 8 * STW72 * 4);
            }
            #pragma unroll
            for (int nt = 0; nt < 4; nt++) {
                u32 b0, b1;
                lds_v2(b0, b1, Bbase + (u32)((nt * 8 * STW72 + kk * 8) * 4));
                #pragma unroll
                for (int mt = 0; mt < 4; mt++)
                    MMA_F16(acc[mt][nt], a[mt][0], a[mt][1], a[mt][2], a[mt][3], b0, b1);
            }
        }

        // ---- pack fp16 half-logits, STS.128 (before the merged barrier) ----
        #pragma unroll
        for (int mt = 0; mt < 4; mt++) {
            #pragma unroll
            for (int half = 0; half < 2; half++) {
                const int row = warp_m * 64 + mt * 16 + half * 8 + gid;
                u32 h0 = pack_h2(acc[mt][0][2 * half], acc[mt][0][2 * half + 1]);
                u32 h1 = pack_h2(acc[mt][1][2 * half], acc[mt][1][2 * half + 1]);
                u32 h2 = pack_h2(acc[mt][2][2 * half], acc[mt][2][2 * half + 1]);
                u32 h3 = pack_h2(acc[mt][3][2 * half], acc[mt][3][2 * half + 1]);
                u32 quad = (u32)(row * 20 + warp_n * 4 + (tid4 ^ ((row >> 1) & 3)));
                sts_v4(sbase + L_OFF + quad * 16, h0, h1, h2, h3);
            }
        }

        __syncthreads();             // merged: W(g) reads done (buffer free) + L(g) visible

        // prefetch W(g+1) (overlaps epilogue)
        if (g < NGROUP - 1) {
            const __half* src = g_Wh + (size_t)(g + 1) * 128 * F;
            #pragma unroll
            for (int j = 0; j < 8; j++) {
                int i = tid + j * NTHREADS;
                int row = i >> 4, c = i & 15;
                cpa16(sbase + W_OFF + (u32)(row * STW72 * 4) + c * 16, src + row * F + c * 8);
            }
            CP_COMMIT();
        }

        // ---- epilogue: 2 (row, tree) tasks per thread ----
        #pragma unroll
        for (int j2 = 0; j2 < 2; j2++) {
            const int tp = jhi * 2 + j2;        // tree-in-group 0..3
            const int t  = g * 4 + tp;
            const float* lc = c_cb.lc + t * 32;
            float s[32];
            #pragma unroll
            for (int q = 0; q < 4; q++) {       // logical quad = writer's tid4
                u32 w0, w1, w2, w3;
                lds_v4(w0, w1, w2, w3, Rrow + (u32)(tp * 4 + (q ^ sr)) * 16);
                const u32 ws[4] = {w0, w1, w2, w3};
                #pragma unroll
                for (int nt = 0; nt < 4; nt++) {
                    __half2 hv = *(__half2*)&ws[nt];
                    const int n = nt * 8 + 2 * q;
                    s[n]     = __low2float(hv);
                    s[n + 1] = __high2float(hv);
                }
            }
            // values are l/2 -> sigmoid = 0.5*tanh + 0.5
            #pragma unroll
            for (int n = 0; n < NI; n++) {
                float th;
                asm("tanh.approx.f32 %0, %1;" : "=f"(th) : "f"(s[n]));
                s[n] = fmaf(0.5f, th, 0.5f);
            }
            float Pn[NI];
            Pn[0] = 1.f;
            #pragma unroll
            for (int i = 0; i < 15; i++) {
                float gg = s[i];
                float pr = Pn[i] * gg;
                Pn[2 * i + 2] = pr;
                Pn[2 * i + 1] = Pn[i] - pr;
            }
            float a0 = 0.f;
            #pragma unroll
            for (int l = 0; l < 16; l++) {      // leaf pair l, parent node 15+l
                const int p = 15 + l;
                float u = fmaf(s[p], lc[2 * l + 1], lc[2 * l]);
                a0 = fmaf(Pn[p], u, a0);
            }
            oc0 += a0;
            oc1 += c_cb.wt[t] - a0;
        }
    }

    // ---- reduce 2 thread-partials per row (X region reused as scratch) ----
    __syncthreads();
    smf[r * 4 + jhi * 2 + 0] = oc0;
    smf[r * 4 + jhi * 2 + 1] = oc1;
    __syncthreads();
    if (tid < TILE_M) {
        float a0 = smf[tid * 4 + 0] + smf[tid * 4 + 2];
        float a1 = smf[tid * 4 + 1] + smf[tid * 4 + 3];
        int row = m0 + tid;
        if (row < B) ((float2*)out)[row] = make_float2(a0, a1);
    }
}

// ---------------- launch ----------------
extern "C" void kernel_launch(void* const* d_in, const int* in_sizes, int n_in,
                              void* d_out, int out_size)
{
    const float* x  = (const float*)d_in[0];  // [B, 128]
    const float* sw = (const float*)d_in[1];  // [T, 31, 128]
    const float* sb = (const float*)d_in[2];  // [T, 31]
    const float* ll = (const float*)d_in[3];  // [T, 32, 2]
    const float* tw = (const float*)d_in[4];  // [T]
    const float* fm = (const float*)d_in[5];  // [T, 128]

    int T = in_sizes[4];
    if (T > TMAX) T = TMAX;
    int B = in_sizes[0] / F;

    cudaFuncSetAttribute(forest_mma, cudaFuncAttributeMaxDynamicSharedMemorySize, SMEM_BYTES);

    prep<<<(NGROUP * 128 * 32 + 255) / 256, 256>>>(sw, fm, sb, ll, tw, T);

    // single merged constant upload (D2D async: graph-capturable)
    void* p = nullptr;
    cudaGetSymbolAddress(&p, g_cb);
    cudaMemcpyToSymbolAsync(c_cb, p, sizeof(ConstBlk), 0,
                            cudaMemcpyDeviceToDevice, 0);

    forest_mma<<<(B + TILE_M - 1) / TILE_M, NTHREADS, SMEM_BYTES>>>(x, (float*)d_out, B);
}